// round 6
// baseline (speedup 1.0000x reference)
#include <cuda_runtime.h>

#define CDIM    64
#define KCODES  1024
#define HWDIM   1024
#define BM      128     // rows per block
#define BK      64      // codes per chunk
#define NCHUNK  (KCODES / BK)
#define NBLOCKS (65536 / BM)
#define NKP     (CDIM / 2)   // 32 kk-pairs

__device__ float d_hn[KCODES];   // 0.5 * ||c_k||^2

__global__ void hn_kernel(const float* __restrict__ cb) {
    int k = blockIdx.x * blockDim.x + threadIdx.x;
    if (k < KCODES) {
        const float4* row = reinterpret_cast<const float4*>(cb + k * CDIM);
        float s = 0.f;
        #pragma unroll
        for (int i = 0; i < CDIM / 4; ++i) {
            float4 v = __ldg(&row[i]);
            s += v.x * v.x + v.y * v.y + v.z * v.z + v.w * v.w;
        }
        d_hn[k] = 0.5f * s;
    }
}

static __forceinline__ __device__ void unpack2(unsigned long long v, float& a, float& b) {
    asm("mov.b64 {%0, %1}, %2;" : "=f"(a), "=f"(b) : "l"(v));
}
// Packed fp32 FMA (FFMA2): two exact fp32 FMAs per instruction.
static __forceinline__ __device__ unsigned long long ffma2(unsigned long long a,
                                                           unsigned long long b,
                                                           unsigned long long c) {
    unsigned long long d;
    asm("fma.rn.f32x2 %0, %1, %2, %3;" : "=l"(d) : "l"(a), "l"(b), "l"(c));
    return d;
}

__global__ __launch_bounds__(256, 2) void vq_kernel(const float* __restrict__ x,
                                                    const float* __restrict__ cb,
                                                    float* __restrict__ out) {
    // x, kk-pair layout: row kp (32 rows), each 128 f32x2 pairs (1024 B)  -> 32 KB
    __shared__ float s_x[NKP * 256];
    // c chunk, kk-pair layout: row kp, 64 f32x2 (512 B), granule-swizzled -> 16 KB
    __shared__ float s_c[NKP * 128];

    const int tid = threadIdx.x;
    const int tx = tid & 15;          // 4 codes per tx
    const int ty = tid >> 4;          // 8 rows per ty
    const int nbase = blockIdx.x * BM;
    const int b = nbase >> 10;        // image index (HW = 1024)
    const int p = nbase & 1023;       // offset within plane
    const float* xin = x + b * (CDIM * HWDIM) + p;

    // swizzled granule bases for compute c loads (granule = 16 B = 2 cols)
    const int G0 = 2 * tx,        G1 = 2 * tx + 1;
    const int g0s = G0 ^ ((G0 >> 1) & 7);     // 2tx ^ (tx&7)
    const int g1s = G1 ^ ((G1 >> 1) & 7);

    // ---- load x tile into kk-pair layout ----
    #pragma unroll
    for (int i = 0; i < 4; ++i) {
        int e  = tid + i * 256;               // 1024 (t, r4) pairs
        int t  = e >> 5;                      // kp row
        int r4 = e & 31;
        float4 a  = *reinterpret_cast<const float4*>(xin + (2 * t)     * HWDIM + r4 * 4);
        float4 bb = *reinterpret_cast<const float4*>(xin + (2 * t + 1) * HWDIM + r4 * 4);
        float* dst = s_x + t * 256 + r4 * 8;
        *reinterpret_cast<float4*>(dst)     = make_float4(a.x, bb.x, a.y, bb.y);
        *reinterpret_cast<float4*>(dst + 4) = make_float4(a.z, bb.z, a.w, bb.w);
    }

    // ---- prefetch chunk 0 of codebook ----
    const float4* cg4 = reinterpret_cast<const float4*>(cb);
    float4 creg[4];
    #pragma unroll
    for (int i = 0; i < 4; ++i) creg[i] = __ldg(&cg4[tid + i * 256]);

    float bestv[8];
    int   besti[8];
    #pragma unroll
    for (int r = 0; r < 8; ++r) { bestv[r] = 3.4e38f; besti[r] = 0; }

    for (int ch = 0; ch < NCHUNK; ++ch) {
        if (ch) __syncthreads();              // previous chunk's readers done
        // ---- store c chunk in kk-pair layout (swizzled granules) ----
        #pragma unroll
        for (int i = 0; i < 4; ++i) {
            int e = tid + i * 256;            // 1024 f4 = 64 codes x 16 kquads
            int j = e >> 4;                   // code row in chunk
            int q = e & 15;                   // kquad: kk = 4q..4q+3 -> kp 2q, 2q+1
            float4 v = creg[i];
            int G  = j >> 1;
            int Gp = G ^ ((G >> 1) & 7) ^ (q & 7);   // (kp>>1)&7 == q&7 for both rows
            float* dst = s_c + (2 * q) * 128 + Gp * 4 + (j & 1) * 2;
            *reinterpret_cast<float2*>(dst)       = make_float2(v.x, v.y);  // kp = 2q
            *reinterpret_cast<float2*>(dst + 128) = make_float2(v.z, v.w);  // kp = 2q+1
        }
        if (ch < NCHUNK - 1) {
            #pragma unroll
            for (int i = 0; i < 4; ++i)
                creg[i] = __ldg(&cg4[(ch + 1) * 1024 + tid + i * 256]);
        }
        __syncthreads();

        unsigned long long acc[8][4];         // [row][col], lanes = (even-kk, odd-kk)
        #pragma unroll
        for (int r = 0; r < 8; ++r)
            #pragma unroll
            for (int m = 0; m < 4; ++m) acc[r][m] = 0ull;

        const char* xb = reinterpret_cast<const char*>(s_x) + ty * 64;
        const char* cbs = reinterpret_cast<const char*>(s_c);
        #pragma unroll 8
        for (int kp = 0; kp < NKP; ++kp) {
            const ulonglong2* xr = reinterpret_cast<const ulonglong2*>(xb + kp * 1024);
            ulonglong2 x0 = xr[0];            // rows 0,1
            ulonglong2 x1 = xr[1];            // rows 2,3
            ulonglong2 x2 = xr[2];            // rows 4,5
            ulonglong2 x3 = xr[3];            // rows 6,7
            const int s = (kp >> 1) & 7;
            ulonglong2 ca = *reinterpret_cast<const ulonglong2*>(
                cbs + kp * 512 + ((g0s ^ s) << 4));   // cols 4tx, 4tx+1
            ulonglong2 cbv = *reinterpret_cast<const ulonglong2*>(
                cbs + kp * 512 + ((g1s ^ s) << 4));   // cols 4tx+2, 4tx+3
            unsigned long long xv0 = x0.x, xv1 = x0.y, xv2 = x1.x, xv3 = x1.y;
            unsigned long long xv4 = x2.x, xv5 = x2.y, xv6 = x3.x, xv7 = x3.y;
            #define ROWFMA(R, XV) \
                acc[R][0] = ffma2(XV, ca.x,  acc[R][0]); \
                acc[R][1] = ffma2(XV, ca.y,  acc[R][1]); \
                acc[R][2] = ffma2(XV, cbv.x, acc[R][2]); \
                acc[R][3] = ffma2(XV, cbv.y, acc[R][3]);
            ROWFMA(0, xv0) ROWFMA(1, xv1) ROWFMA(2, xv2) ROWFMA(3, xv3)
            ROWFMA(4, xv4) ROWFMA(5, xv5) ROWFMA(6, xv6) ROWFMA(7, xv7)
            #undef ROWFMA
        }

        // ---- running argmin (cols ascending -> first-min semantics) ----
        #pragma unroll
        for (int m = 0; m < 4; ++m) {
            int col = ch * BK + tx * 4 + m;
            float hn = __ldg(&d_hn[col]);
            #pragma unroll
            for (int r = 0; r < 8; ++r) {
                float e0, e1;
                unpack2(acc[r][m], e0, e1);
                float sc = hn - (e0 + e1);
                if (sc < bestv[r]) { bestv[r] = sc; besti[r] = col; }
            }
        }
    }

    // ---- reduce across the 16 tx lanes (same rows); lower index wins ties ----
    #pragma unroll
    for (int r = 0; r < 8; ++r) {
        float v = bestv[r];
        int idx = besti[r];
        #pragma unroll
        for (int off = 8; off > 0; off >>= 1) {
            float ov = __shfl_down_sync(0xffffffffu, v, off, 16);
            int   oi = __shfl_down_sync(0xffffffffu, idx, off, 16);
            if (ov < v || (ov == v && oi < idx)) { v = ov; idx = oi; }
        }
        besti[r] = idx;
    }

    __syncthreads();
    int* s_idx = reinterpret_cast<int*>(s_c);
    if (tx == 0) {
        #pragma unroll
        for (int r = 0; r < 8; ++r) s_idx[ty * 8 + r] = besti[r];
    }
    __syncthreads();

    // ---- epilogue: gather code vectors, write NCHW coalesced float4 ----
    float* outp = out + b * (CDIM * HWDIM) + p;
    #pragma unroll
    for (int i = 0; i < 8; ++i) {
        int e   = tid + i * 256;             // 2048 float4
        int chn = e >> 5;                    // channel (32 f4 per channel)
        int r4  = e & 31;
        int i0 = s_idx[r4 * 4 + 0];
        int i1 = s_idx[r4 * 4 + 1];
        int i2 = s_idx[r4 * 4 + 2];
        int i3 = s_idx[r4 * 4 + 3];
        float4 o;
        o.x = __ldg(&cb[i0 * CDIM + chn]);
        o.y = __ldg(&cb[i1 * CDIM + chn]);
        o.z = __ldg(&cb[i2 * CDIM + chn]);
        o.w = __ldg(&cb[i3 * CDIM + chn]);
        *reinterpret_cast<float4*>(outp + chn * HWDIM + r4 * 4) = o;
    }
}

extern "C" void kernel_launch(void* const* d_in, const int* in_sizes, int n_in,
                              void* d_out, int out_size) {
    const float* x  = (const float*)d_in[0];   // inputs  [64,64,32,32]
    const float* cb = (const float*)d_in[1];   // codebook [1024,64]
    float* out = (float*)d_out;
    hn_kernel<<<4, 256>>>(cb);
    vq_kernel<<<NBLOCKS, 256>>>(x, cb, out);
}